// round 10
// baseline (speedup 1.0000x reference)
#include <cuda_runtime.h>
#include <cstdint>

#define MARGIN 0.1f
#define TPB 256
#define WPB (TPB / 32)   // warps (rows) per CTA
#define P1U 4            // pass-1: int4 loads per lane between ballots (512 elems)

// Global accumulators. Zero at module load; hinge_final_kernel resets them to
// zero after each launch, so every invocation (correctness call, capture call,
// each graph replay) observes identical initial state.
__device__ float g_total;
__device__ float g_count;

__global__ void __launch_bounds__(TPB) hinge_row_kernel(
    const float* __restrict__ scores,
    const int* __restrict__ lens,
    const int* __restrict__ labels,
    int L, int B)
{
    const int lane = threadIdx.x & 31;
    const int row = blockIdx.x * WPB + (threadIdx.x >> 5);
    if (row >= B) return;

    const int len = lens[row];          // warp-uniform
    if (len <= 0) return;               // no valid observation, contributes 0

    const size_t base = (size_t)row * (size_t)L;
    const float*  __restrict__ srow  = scores + base;
    const float4* __restrict__ srow4 = (const float4*)srow;
    const int4*   __restrict__ lrow4 = (const int4*)(labels + base);
    const int nv = (len + 3) >> 2;      // live float4/int4 prefix

    // ---- pass 1: scan labels for the (at most one) positive.
    //      P1U independent int4 loads per lane issued before each ballot:
    //      deep MLP, 1 latency round-trip per 512 elements. ----
    float pos_sum = 0.0f;
    int   pos_cnt = 0;
    for (int v0 = 0; v0 < nv; v0 += 32 * P1U) {
        int4 lv[P1U];
#pragma unroll
        for (int u = 0; u < P1U; u++) {
            const int v = v0 + u * 32 + lane;
            lv[u] = (v < nv) ? lrow4[v] : make_int4(0, 0, 0, 0);
        }
        bool found = false;
#pragma unroll
        for (int u = 0; u < P1U; u++) {
            const int v = v0 + u * 32 + lane;
            const int j0 = v << 2;
            const int le[4] = { lv[u].x, lv[u].y, lv[u].z, lv[u].w };
#pragma unroll
            for (int e = 0; e < 4; e++) {
                const int j = j0 + e;
                if (j < len && le[e] == 1) {
                    pos_sum += srow[j];     // rare predicated gather
                    pos_cnt++;
                    found = true;
                }
            }
        }
        if (__ballot_sync(0xFFFFFFFFu, found)) break;   // ≤1 positive per row
    }
    // butterfly reduce -> every lane holds totals
#pragma unroll
    for (int o = 16; o > 0; o >>= 1) {
        pos_sum += __shfl_xor_sync(0xFFFFFFFFu, pos_sum, o);
        pos_cnt += __shfl_xor_sync(0xFFFFFFFFu, pos_cnt, o);
    }
    const float chosen = (pos_cnt > 0) ? pos_sum : -MARGIN;

    // ---- pass 2: hinge over ALL valid elements, 2-way unrolled for MLP.
    //      (Labels not needed: the positive's hinge is exactly MARGIN,
    //      subtracted at the end.) ----
    float hs = 0.0f;
    for (int v = lane; v < nv; v += 64) {
        const int v2 = v + 32;
        const bool has2 = (v2 < nv);
        const float4 a = srow4[v];
        float4 b = make_float4(0.f, 0.f, 0.f, 0.f);
        if (has2) b = srow4[v2];

        {
            const int j0 = v << 2;
            const float se[4] = { a.x, a.y, a.z, a.w };
#pragma unroll
            for (int e = 0; e < 4; e++)
                if (j0 + e < len)
                    hs += fmaxf(MARGIN + se[e] - chosen, 0.0f);
        }
        if (has2) {
            const int j0 = v2 << 2;
            const float se[4] = { b.x, b.y, b.z, b.w };
#pragma unroll
            for (int e = 0; e < 4; e++)
                if (j0 + e < len)
                    hs += fmaxf(MARGIN + se[e] - chosen, 0.0f);
        }
    }
#pragma unroll
    for (int o = 16; o > 0; o >>= 1)
        hs += __shfl_down_sync(0xFFFFFFFFu, hs, o);

    if (lane == 0) {
        const int neg_cnt = len - pos_cnt;       // valid elems minus positives
        if (neg_cnt > 0) {                       // valid_obs = (len>0) & has_neg
            const float hs_neg = hs - MARGIN * (float)pos_cnt;
            atomicAdd(&g_total, hs_neg / (float)neg_cnt);
            atomicAdd(&g_count, 1.0f);
        }
    }
}

__global__ void hinge_final_kernel(float* __restrict__ out)
{
    const float T = g_total;
    const float C = g_count;
    out[0] = (C > 0.0f) ? (T / fmaxf(C, 1.0f)) : 0.0f;
    // Reset for the next launch / graph replay.
    g_total = 0.0f;
    g_count = 0.0f;
}

extern "C" void kernel_launch(void* const* d_in, const int* in_sizes, int n_in,
                              void* d_out, int out_size)
{
    const float* scores = (const float*)d_in[0];
    const int*   lens   = (const int*)d_in[1];
    const int*   labels = (const int*)d_in[2];
    float* out = (float*)d_out;

    const int B = in_sizes[1];            // candidate_lengths element count
    const int L = in_sizes[0] / B;        // 2048

    const int nblk = (B + WPB - 1) / WPB;
    hinge_row_kernel<<<nblk, TPB>>>(scores, lens, labels, L, B);
    hinge_final_kernel<<<1, 1>>>(out);
}

// round 11
// speedup vs baseline: 1.2914x; 1.2914x over previous
#include <cuda_runtime.h>
#include <cstdint>

#define MARGIN 0.1f
#define TPB 32           // ONE warp per CTA: a finished row frees its slot
#define P1U 4            // pass-1: int4 loads per lane between ballots
#define NSLOT 32

// Scattered accumulator slots (128B apart -> distinct L2 slices, no atomic
// serialization at one address). Zero at module load; hinge_final_kernel
// resets them after each launch so every invocation sees identical state.
struct Slot { float total; float count; float pad[30]; };   // 128 bytes
__device__ Slot g_slots[NSLOT];

__global__ void __launch_bounds__(TPB) hinge_row_kernel(
    const float* __restrict__ scores,
    const int* __restrict__ lens,
    const int* __restrict__ labels,
    int L, int B)
{
    const int lane = threadIdx.x;
    const int row = blockIdx.x;
    if (row >= B) return;

    const int len = lens[row];          // warp-uniform
    if (len <= 0) return;               // no valid observation, contributes 0

    const size_t base = (size_t)row * (size_t)L;
    const float*  __restrict__ srow  = scores + base;
    const float4* __restrict__ srow4 = (const float4*)srow;
    const int4*   __restrict__ lrow4 = (const int4*)(labels + base);
    const int nv = (len + 3) >> 2;      // live float4/int4 prefix

    // ---- pass 1: scan labels for the (at most one) positive; early exit.
    //      P1U independent int4 loads issued before each ballot. ----
    float pos_sum = 0.0f;
    int   pos_cnt = 0;
    for (int v0 = 0; v0 < nv; v0 += 32 * P1U) {
        int4 lv[P1U];
#pragma unroll
        for (int u = 0; u < P1U; u++) {
            const int v = v0 + u * 32 + lane;
            lv[u] = (v < nv) ? lrow4[v] : make_int4(0, 0, 0, 0);
        }
        bool found = false;
#pragma unroll
        for (int u = 0; u < P1U; u++) {
            const int v = v0 + u * 32 + lane;
            const int j0 = v << 2;
            const int le[4] = { lv[u].x, lv[u].y, lv[u].z, lv[u].w };
#pragma unroll
            for (int e = 0; e < 4; e++) {
                const int j = j0 + e;
                if (j < len && le[e] == 1) {
                    pos_sum += srow[j];     // rare predicated gather
                    pos_cnt++;
                    found = true;
                }
            }
        }
        if (__ballot_sync(0xFFFFFFFFu, found)) break;   // ≤1 positive per row
    }
#pragma unroll
    for (int o = 16; o > 0; o >>= 1) {
        pos_sum += __shfl_xor_sync(0xFFFFFFFFu, pos_sum, o);
        pos_cnt += __shfl_xor_sync(0xFFFFFFFFu, pos_cnt, o);
    }
    const float chosen = (pos_cnt > 0) ? pos_sum : -MARGIN;

    // ---- pass 2: hinge over ALL valid elements, 4-way unrolled.
    //      (Labels not needed: the positive's hinge is exactly MARGIN,
    //      subtracted at the end.) ----
    float hs = 0.0f;
    for (int v0 = 0; v0 < nv; v0 += 32 * 4) {
        float4 a[4];
#pragma unroll
        for (int u = 0; u < 4; u++) {
            const int v = v0 + u * 32 + lane;
            a[u] = (v < nv) ? srow4[v] : make_float4(0.f, 0.f, 0.f, 0.f);
        }
#pragma unroll
        for (int u = 0; u < 4; u++) {
            const int j0 = (v0 + u * 32 + lane) << 2;
            const float se[4] = { a[u].x, a[u].y, a[u].z, a[u].w };
#pragma unroll
            for (int e = 0; e < 4; e++)
                if (j0 + e < len)
                    hs += fmaxf(MARGIN + se[e] - chosen, 0.0f);
        }
    }
#pragma unroll
    for (int o = 16; o > 0; o >>= 1)
        hs += __shfl_down_sync(0xFFFFFFFFu, hs, o);

    if (lane == 0) {
        const int neg_cnt = len - pos_cnt;       // valid elems minus positives
        if (neg_cnt > 0) {                       // valid_obs = (len>0) & has_neg
            const float hs_neg = hs - MARGIN * (float)pos_cnt;
            Slot* sl = &g_slots[row & (NSLOT - 1)];
            atomicAdd(&sl->total, hs_neg / (float)neg_cnt);
            atomicAdd(&sl->count, 1.0f);
        }
    }
}

__global__ void hinge_final_kernel(float* __restrict__ out)
{
    float T = 0.0f, C = 0.0f;
#pragma unroll
    for (int i = 0; i < NSLOT; i++) {
        T += g_slots[i].total;
        C += g_slots[i].count;
        g_slots[i].total = 0.0f;      // reset for next launch / graph replay
        g_slots[i].count = 0.0f;
    }
    out[0] = (C > 0.0f) ? (T / fmaxf(C, 1.0f)) : 0.0f;
}

extern "C" void kernel_launch(void* const* d_in, const int* in_sizes, int n_in,
                              void* d_out, int out_size)
{
    const float* scores = (const float*)d_in[0];
    const int*   lens   = (const int*)d_in[1];
    const int*   labels = (const int*)d_in[2];
    float* out = (float*)d_out;

    const int B = in_sizes[1];            // candidate_lengths element count
    const int L = in_sizes[0] / B;        // 2048

    hinge_row_kernel<<<B, TPB>>>(scores, lens, labels, L, B);
    hinge_final_kernel<<<1, 1>>>(out);
}

// round 12
// speedup vs baseline: 1.4288x; 1.1064x over previous
#include <cuda_runtime.h>
#include <cstdint>

#define MARGIN 0.1f
#define TPB 64           // 2 warps/CTA: 2 rows per CTA -> 64 resident warps/SM
#define RPB (TPB / 32)   // rows per CTA
#define P1U 4            // pass-1: int4 loads per lane between ballots
#define NSLOT 32

// Scattered accumulator slots (128B apart -> distinct L2 slices, no atomic
// serialization at one address). Zero at module load; hinge_final_kernel
// resets them after each launch so every invocation sees identical state.
struct Slot { float total; float count; float pad[30]; };   // 128 bytes
__device__ Slot g_slots[NSLOT];

__global__ void __launch_bounds__(TPB) hinge_row_kernel(
    const float* __restrict__ scores,
    const int* __restrict__ lens,
    const int* __restrict__ labels,
    int L, int B)
{
    const int lane = threadIdx.x & 31;
    const int row = blockIdx.x * RPB + (threadIdx.x >> 5);
    if (row >= B) return;

    const int len = lens[row];          // warp-uniform
    if (len <= 0) return;               // no valid observation, contributes 0

    const size_t base = (size_t)row * (size_t)L;
    const float*  __restrict__ srow  = scores + base;
    const float4* __restrict__ srow4 = (const float4*)srow;
    const int4*   __restrict__ lrow4 = (const int4*)(labels + base);
    const int nv = (len + 3) >> 2;      // live float4/int4 prefix

    // ---- pass 1: scan labels for the (at most one) positive; early exit.
    //      P1U independent int4 loads issued before each ballot. ----
    float pos_sum = 0.0f;
    int   pos_cnt = 0;
    for (int v0 = 0; v0 < nv; v0 += 32 * P1U) {
        int4 lv[P1U];
#pragma unroll
        for (int u = 0; u < P1U; u++) {
            const int v = v0 + u * 32 + lane;
            lv[u] = (v < nv) ? lrow4[v] : make_int4(0, 0, 0, 0);
        }
        bool found = false;
#pragma unroll
        for (int u = 0; u < P1U; u++) {
            const int v = v0 + u * 32 + lane;
            const int j0 = v << 2;
            const int le[4] = { lv[u].x, lv[u].y, lv[u].z, lv[u].w };
#pragma unroll
            for (int e = 0; e < 4; e++) {
                const int j = j0 + e;
                if (j < len && le[e] == 1) {
                    pos_sum += srow[j];     // rare predicated gather
                    pos_cnt++;
                    found = true;
                }
            }
        }
        if (__ballot_sync(0xFFFFFFFFu, found)) break;   // ≤1 positive per row
    }
#pragma unroll
    for (int o = 16; o > 0; o >>= 1) {
        pos_sum += __shfl_xor_sync(0xFFFFFFFFu, pos_sum, o);
        pos_cnt += __shfl_xor_sync(0xFFFFFFFFu, pos_cnt, o);
    }
    const float chosen = (pos_cnt > 0) ? pos_sum : -MARGIN;

    // ---- pass 2: hinge over ALL valid elements, 4-way unrolled.
    //      (Labels not needed: the positive's hinge is exactly MARGIN,
    //      subtracted at the end.) ----
    float hs = 0.0f;
    for (int v0 = 0; v0 < nv; v0 += 32 * 4) {
        float4 a[4];
#pragma unroll
        for (int u = 0; u < 4; u++) {
            const int v = v0 + u * 32 + lane;
            a[u] = (v < nv) ? srow4[v] : make_float4(0.f, 0.f, 0.f, 0.f);
        }
#pragma unroll
        for (int u = 0; u < 4; u++) {
            const int j0 = (v0 + u * 32 + lane) << 2;
            const float se[4] = { a[u].x, a[u].y, a[u].z, a[u].w };
#pragma unroll
            for (int e = 0; e < 4; e++)
                if (j0 + e < len)
                    hs += fmaxf(MARGIN + se[e] - chosen, 0.0f);
        }
    }
#pragma unroll
    for (int o = 16; o > 0; o >>= 1)
        hs += __shfl_down_sync(0xFFFFFFFFu, hs, o);

    if (lane == 0) {
        const int neg_cnt = len - pos_cnt;       // valid elems minus positives
        if (neg_cnt > 0) {                       // valid_obs = (len>0) & has_neg
            const float hs_neg = hs - MARGIN * (float)pos_cnt;
            Slot* sl = &g_slots[row & (NSLOT - 1)];
            atomicAdd(&sl->total, hs_neg / (float)neg_cnt);
            atomicAdd(&sl->count, 1.0f);
        }
    }
}

__global__ void hinge_final_kernel(float* __restrict__ out)
{
    float T = 0.0f, C = 0.0f;
#pragma unroll
    for (int i = 0; i < NSLOT; i++) {
        T += g_slots[i].total;
        C += g_slots[i].count;
        g_slots[i].total = 0.0f;      // reset for next launch / graph replay
        g_slots[i].count = 0.0f;
    }
    out[0] = (C > 0.0f) ? (T / fmaxf(C, 1.0f)) : 0.0f;
}

extern "C" void kernel_launch(void* const* d_in, const int* in_sizes, int n_in,
                              void* d_out, int out_size)
{
    const float* scores = (const float*)d_in[0];
    const int*   lens   = (const int*)d_in[1];
    const int*   labels = (const int*)d_in[2];
    float* out = (float*)d_out;

    const int B = in_sizes[1];            // candidate_lengths element count
    const int L = in_sizes[0] / B;        // 2048

    const int nblk = (B + RPB - 1) / RPB;
    hinge_row_kernel<<<nblk, TPB>>>(scores, lens, labels, L, B);
    hinge_final_kernel<<<1, 1>>>(out);
}

// round 15
// speedup vs baseline: 1.5706x; 1.0993x over previous
#include <cuda_runtime.h>
#include <cstdint>

#define MARGIN 0.1f
#define TPB 64           // 2 warps, ONE row per CTA: perfect slot backfill
#define P1U 2            // pass-1: int4 loads per thread between votes (512 elems/chunk)
#define P2U 4            // pass-2 unroll
#define NSLOT 32

// Scattered accumulator slots (128B apart -> distinct L2 slices, no atomic
// serialization at one address). Zero at module load; hinge_final_kernel
// resets them after each launch so every invocation sees identical state.
struct Slot { float total; float count; float pad[30]; };   // 128 bytes
__device__ Slot g_slots[NSLOT];

__global__ void __launch_bounds__(TPB) hinge_row_kernel(
    const float* __restrict__ scores,
    const int* __restrict__ lens,
    const int* __restrict__ labels,
    int L, int B)
{
    const int t = threadIdx.x;
    const int lane = t & 31;
    const int wid = t >> 5;
    const int row = blockIdx.x;
    if (row >= B) return;

    const int len = lens[row];          // CTA-uniform
    if (len <= 0) return;               // no valid observation, contributes 0

    const size_t base = (size_t)row * (size_t)L;
    const float*  __restrict__ srow  = scores + base;
    const float4* __restrict__ srow4 = (const float4*)srow;
    const int4*   __restrict__ lrow4 = (const int4*)(labels + base);
    const int nv = (len + 3) >> 2;      // live float4/int4 prefix

    __shared__ float sh_ps[2];
    __shared__ int   sh_pc[2];
    __shared__ float sh_hs[2];

    // ---- pass 1: both warps scan labels for the (at most one) positive;
    //      block-wide vote to early-exit. ----
    float pos_sum = 0.0f;
    int   pos_cnt = 0;
    int   found = 0;
    for (int v0 = 0; v0 < nv; v0 += TPB * P1U) {
        int4 lv[P1U];
#pragma unroll
        for (int u = 0; u < P1U; u++) {
            const int v = v0 + u * TPB + t;
            lv[u] = (v < nv) ? lrow4[v] : make_int4(0, 0, 0, 0);
        }
#pragma unroll
        for (int u = 0; u < P1U; u++) {
            const int v = v0 + u * TPB + t;
            const int j0 = v << 2;
            const int le[4] = { lv[u].x, lv[u].y, lv[u].z, lv[u].w };
#pragma unroll
            for (int e = 0; e < 4; e++) {
                const int j = j0 + e;
                if (j < len && le[e] == 1) {
                    pos_sum += srow[j];     // rare predicated gather
                    pos_cnt++;
                    found = 1;
                }
            }
        }
        if (__syncthreads_or(found)) break;  // ≤1 positive per row
    }
    // block reduce pos_sum / pos_cnt (2 warps)
#pragma unroll
    for (int o = 16; o > 0; o >>= 1) {
        pos_sum += __shfl_xor_sync(0xFFFFFFFFu, pos_sum, o);
        pos_cnt += __shfl_xor_sync(0xFFFFFFFFu, pos_cnt, o);
    }
    if (lane == 0) { sh_ps[wid] = pos_sum; sh_pc[wid] = pos_cnt; }
    __syncthreads();
    const float ps = sh_ps[0] + sh_ps[1];
    const int   pc = sh_pc[0] + sh_pc[1];
    const float chosen = (pc > 0) ? ps : -MARGIN;

    // ---- pass 2: hinge over ALL valid elements, unrolled for MLP.
    //      (Labels not needed: the positive's hinge is exactly MARGIN,
    //      subtracted at the end.) ----
    float hs = 0.0f;
    for (int v0 = 0; v0 < nv; v0 += TPB * P2U) {
        float4 a[P2U];
#pragma unroll
        for (int u = 0; u < P2U; u++) {
            const int v = v0 + u * TPB + t;
            a[u] = (v < nv) ? srow4[v] : make_float4(0.f, 0.f, 0.f, 0.f);
        }
#pragma unroll
        for (int u = 0; u < P2U; u++) {
            const int j0 = (v0 + u * TPB + t) << 2;
            const float se[4] = { a[u].x, a[u].y, a[u].z, a[u].w };
#pragma unroll
            for (int e = 0; e < 4; e++)
                if (j0 + e < len)
                    hs += fmaxf(MARGIN + se[e] - chosen, 0.0f);
        }
    }
#pragma unroll
    for (int o = 16; o > 0; o >>= 1)
        hs += __shfl_down_sync(0xFFFFFFFFu, hs, o);
    if (lane == 0) sh_hs[wid] = hs;
    __syncthreads();

    if (t == 0) {
        const float h = sh_hs[0] + sh_hs[1];
        const int neg_cnt = len - pc;            // valid elems minus positives
        if (neg_cnt > 0) {                       // valid_obs = (len>0) & has_neg
            const float hs_neg = h - MARGIN * (float)pc;
            Slot* sl = &g_slots[row & (NSLOT - 1)];
            atomicAdd(&sl->total, hs_neg / (float)neg_cnt);
            atomicAdd(&sl->count, 1.0f);
        }
    }
}

__global__ void __launch_bounds__(32) hinge_final_kernel(float* __restrict__ out)
{
    const int i = threadIdx.x;                 // 32 threads, one slot each
    float T = g_slots[i].total;
    float C = g_slots[i].count;
    g_slots[i].total = 0.0f;                   // reset for next launch / replay
    g_slots[i].count = 0.0f;
#pragma unroll
    for (int o = 16; o > 0; o >>= 1) {
        T += __shfl_down_sync(0xFFFFFFFFu, T, o);
        C += __shfl_down_sync(0xFFFFFFFFu, C, o);
    }
    if (i == 0)
        out[0] = (C > 0.0f) ? (T / fmaxf(C, 1.0f)) : 0.0f;
}

extern "C" void kernel_launch(void* const* d_in, const int* in_sizes, int n_in,
                              void* d_out, int out_size)
{
    const float* scores = (const float*)d_in[0];
    const int*   lens   = (const int*)d_in[1];
    const int*   labels = (const int*)d_in[2];
    float* out = (float*)d_out;

    const int B = in_sizes[1];            // candidate_lengths element count
    const int L = in_sizes[0] / B;        // 2048

    hinge_row_kernel<<<B, TPB>>>(scores, lens, labels, L, B);
    hinge_final_kernel<<<1, 32>>>(out);
}